// round 17
// baseline (speedup 1.0000x reference)
#include <cuda_runtime.h>
#include <cuda_bf16.h>
#include <cstdint>
#include <cstddef>

// LSTM_824633721296: 2-layer LSTM (B=1024, T=512, I=8, H=64) + FC (O=10)
// Round-17: ONE barrier per step. Weight rows permuted gate-major (row r =
// gate r%4 of hidden r/4) so each warp's D-frags hold all 4 gates of its 4
// hiddens; a 4x4 shfl.xor transpose gives every thread its (i,f,g,o) quad in
// registers -> elem runs in-register, gate smem buffers deleted. B1 (h state)
// and xs double-buffered (read p, write p^1). mma.sync m16n8k16, bf16 weights
// register-resident, h hi/lo 2-term. 512 threads, 1 m-tile/warp.

#define BT       8
#define NB       128
#define NTHREADS 512
#define HID      64
#define TSTEPS   512
#define IDIM     8
#define ODIM     10

#define W0S  144            // W0 staging row stride bytes
#define W1S  256            // W1 staging row stride bytes (XOR-swizzled)
#define B1S  272            // B1 row stride bytes ([h0 | h1] bf16 + pad)
#define B1BUF (8 * B1S)     // one B1 buffer = 2176 B

// smem byte offsets
#define SM_W0H 0            // [256][144] staging (prologue only)
#define SM_W1H 36864        // [256][256] swizzled staging
#define SM_B1H 102400       // 2 x [8][272]  [h0 | h1] hi (double-buffered)
#define SM_B1L 106752       // 2 x [8][272]  lo
#define SM_XS  111104       // f32 2 x [8][8]
#define SM_H1F 111616       // f32 [8][64]
#define SMEM_BYTES 113664

__device__ __forceinline__ void ldmx4(uint32_t r[4], uint32_t addr) {
    asm volatile("ldmatrix.sync.aligned.m8n8.x4.shared.b16 {%0,%1,%2,%3}, [%4];"
                 : "=r"(r[0]), "=r"(r[1]), "=r"(r[2]), "=r"(r[3]) : "r"(addr));
}
__device__ __forceinline__ void mma16816(float d[4], const uint32_t a[4],
                                         uint32_t b0, uint32_t b1) {
    asm volatile("mma.sync.aligned.m16n8k16.row.col.f32.bf16.bf16.f32 "
                 "{%0,%1,%2,%3}, {%4,%5,%6,%7}, {%8,%9}, {%0,%1,%2,%3};"
                 : "+f"(d[0]), "+f"(d[1]), "+f"(d[2]), "+f"(d[3])
                 : "r"(a[0]), "r"(a[1]), "r"(a[2]), "r"(a[3]), "r"(b0), "r"(b1));
}
__device__ __forceinline__ float tanha(float x) {
    float r; asm("tanh.approx.f32 %0, %1;" : "=f"(r) : "f"(x)); return r;
}
__device__ __forceinline__ float sigm_(float x) {
    return fmaf(0.5f, tanha(0.5f * x), 0.5f);
}
__device__ __forceinline__ void split_bf16(float v, __nv_bfloat16& hi, __nv_bfloat16& lo) {
    hi = __float2bfloat16(v);
    lo = __float2bfloat16(v - __bfloat162float(hi));
}
// 4x4 transpose within 4-lane groups (lanes differing in bits 2-3).
// g = (lane>>2)&3. After: V[gamma] = original V(gamma-th thread of group)[g].
__device__ __forceinline__ void transpose4(float V[4], int g) {
    float s0 = (g & 2) ? V[0] : V[2];
    float s1 = (g & 2) ? V[1] : V[3];
    s0 = __shfl_xor_sync(0xFFFFFFFFu, s0, 8);
    s1 = __shfl_xor_sync(0xFFFFFFFFu, s1, 8);
    if (g & 2) { V[0] = s0; V[1] = s1; } else { V[2] = s0; V[3] = s1; }
    float u0 = (g & 1) ? V[0] : V[1];
    float u1 = (g & 1) ? V[2] : V[3];
    u0 = __shfl_xor_sync(0xFFFFFFFFu, u0, 4);
    u1 = __shfl_xor_sync(0xFFFFFFFFu, u1, 4);
    if (g & 1) { V[0] = u0; V[2] = u1; } else { V[1] = u0; V[3] = u1; }
}

extern __shared__ char smem[];

__global__ void __launch_bounds__(NTHREADS, 1)
lstm_wmma_kernel(const float* __restrict__ x,
                 const float* __restrict__ w_ih0, const float* __restrict__ w_hh0,
                 const float* __restrict__ b_ih0, const float* __restrict__ b_hh0,
                 const float* __restrict__ w_ih1, const float* __restrict__ w_hh1,
                 const float* __restrict__ b_ih1, const float* __restrict__ b_hh1,
                 const float* __restrict__ w_fc,  const float* __restrict__ b_fc,
                 float* __restrict__ out)
{
    const int tid  = threadIdx.x;
    const int w    = tid >> 5;          // warp 0..15 = m-tile (hiddens 4w..4w+3)
    const int lane = tid & 31;
    const int b0   = blockIdx.x * BT;

    uint32_t smb;
    asm("{ .reg .u64 t; cvta.to.shared.u64 t, %1; cvt.u32.u64 %0, t; }"
        : "=r"(smb) : "l"(smem));

    // ---- zero BOTH B1 buffers (h starts 0; pads must be 0) ----
    for (int i = tid; i < (2 * B1BUF) / 4; i += NTHREADS) {
        ((uint32_t*)(smem + SM_B1H))[i] = 0;
        ((uint32_t*)(smem + SM_B1L))[i] = 0;
    }

    // ---- stage weights gate-major permuted: staged row r <- orig (r%4)*64 + r/4 ----
    for (int i = tid; i < 256 * 64; i += NTHREADS) {
        int r = i >> 6, k = i & 63;
        int o = (r & 3) * 64 + (r >> 2);
        *(__nv_bfloat16*)(smem + SM_W0H + r * W0S + k * 2) =
            __float2bfloat16(w_hh0[o * 64 + k]);
    }
    for (int i = tid; i < 256 * 128; i += NTHREADS) {
        int r = i >> 7, k = i & 127;
        int o = (r & 3) * 64 + (r >> 2);
        float v = (k < 64) ? w_ih1[o * 64 + k] : w_hh1[o * 64 + (k - 64)];
        uint32_t off = (uint32_t)(k * 2) ^ (uint32_t)((r & 7) << 4);
        *(__nv_bfloat16*)(smem + SM_W1H + r * W1S + off) = __float2bfloat16(v);
    }

    float* xsf = (float*)(smem + SM_XS);   // 2 x [8][8]
    float* h1f = (float*)(smem + SM_H1F);

    // x(t=0) -> xs buffer 0
    if (tid < 16) {
        int b = tid >> 1, qq = tid & 1;
        float4 v = *(const float4*)(x + (size_t)(b0 + b) * TSTEPS * IDIM + qq * 4);
        *(float4*)(xsf + b * 8 + qq * 4) = v;
    }

    // mma lane geometry
    const int mb    = 16 * w;
    const int aRow  = lane & 15;
    const int aHalf = lane >> 4;
    const int bn    = lane >> 2;
    const int bq    = lane & 3;
    const int dq    = lane & 3;        // batch pair
    const int dg    = lane >> 2;       // 0..7 = 4a+g
    const int ga    = dg >> 2;         // a: hidden sub (0/1)
    const int gg    = dg & 3;          // g: gate index owned pre-transpose

    // D-owner rows (permuted index space) and their orig-row constants
    const int gbA = 2 * dq, gbB = gbA + 1;
    const int rowA = mb + dg, rowB = mb + dg + 8;
    const int oA = (rowA & 3) * 64 + (rowA >> 2);
    const int oB = (rowB & 3) * 64 + (rowB >> 2);
    const float bias0A = b_ih0[oA] + b_hh0[oA];
    const float bias0B = b_ih0[oB] + b_hh0[oB];
    const float bias1A = b_ih1[oA] + b_hh1[oA];
    const float bias1B = b_ih1[oB] + b_hh1[oB];
    float wxa[8], wxb[8];
    #pragma unroll
    for (int q = 0; q < 8; q++) {
        wxa[q] = w_ih0[oA * IDIM + q];
        wxb[q] = w_ih0[oB * IDIM + q];
    }

    // elem ownership after transpose: batch bT, hidden hT
    const int bT = 2 * dq + (gg & 1);
    const int hT = 4 * w + ga + 2 * (gg >> 1);
    float c0 = 0.f, c1 = 0.f;

    __syncthreads();

    // ---- A-frags register-resident for all steps ----
    uint32_t a0h[4][4];
    uint32_t a1h[8][4];
    #pragma unroll
    for (int kt = 0; kt < 4; kt++) {
        uint32_t ro = (uint32_t)(mb + aRow) * W0S + kt * 32 + aHalf * 16;
        ldmx4(a0h[kt], smb + SM_W0H + ro);
    }
    #pragma unroll
    for (int kt = 0; kt < 8; kt++) {
        int row = mb + aRow;
        uint32_t off = (uint32_t)(kt * 32 + aHalf * 16) ^ (uint32_t)((row & 7) << 4);
        ldmx4(a1h[kt], smb + SM_W1H + (uint32_t)row * W1S + off);
    }
    __syncthreads();

    for (int t = 0; t < TSTEPS; t++) {
        const int p = t & 1;
        const char* rH = smem + SM_B1H + p * B1BUF;        // read buffers
        const char* rL = smem + SM_B1L + p * B1BUF;
        char* wH = smem + SM_B1H + (p ^ 1) * B1BUF;        // write buffers
        char* wL = smem + SM_B1L + (p ^ 1) * B1BUF;
        const float* xr = xsf + p * 64;
        float* xw = xsf + (p ^ 1) * 64;

        // x(t+1) prefetch (LDG now, STS at end of phase into xs[p^1])
        float4 xpre = make_float4(0.f, 0.f, 0.f, 0.f);
        const bool doPre = (tid < 16) && (t + 1 < TSTEPS);
        if (doPre) {
            int b = tid >> 1, qq = tid & 1;
            xpre = *(const float4*)(x + (size_t)(b0 + b) * TSTEPS * IDIM
                                      + (size_t)(t + 1) * IDIM + qq * 4);
        }

        // ---- xg(t): exact fp32, per D-owner elements ----
        float4 vA0 = ((const float4*)xr)[gbA * 2];
        float4 vA1 = ((const float4*)xr)[gbA * 2 + 1];
        float4 vB0 = ((const float4*)xr)[gbB * 2];
        float4 vB1 = ((const float4*)xr)[gbB * 2 + 1];
        float xA[8] = {vA0.x, vA0.y, vA0.z, vA0.w, vA1.x, vA1.y, vA1.z, vA1.w};
        float xB[8] = {vB0.x, vB0.y, vB0.z, vB0.w, vB1.x, vB1.y, vB1.z, vB1.w};
        float xgAa = 0.f, xgBa = 0.f, xgAb = 0.f, xgBb = 0.f;
        #pragma unroll
        for (int q = 0; q < 8; q++) {
            xgAa = fmaf(xA[q], wxa[q], xgAa);
            xgBa = fmaf(xB[q], wxa[q], xgBa);
            xgAb = fmaf(xA[q], wxb[q], xgAb);
            xgBb = fmaf(xB[q], wxb[q], xgBb);
        }

        // ---- GEMM0(t) + GEMM1(t-1) ----
        float d0h[4] = {0,0,0,0}, d0l[4] = {0,0,0,0};
        float d1h[4] = {0,0,0,0}, d1l[4] = {0,0,0,0};
        #pragma unroll
        for (int kt = 0; kt < 8; kt++) {
            uint32_t boff = bn * B1S + kt * 32 + bq * 4;
            uint32_t bh0 = *(const uint32_t*)(rH + boff);
            uint32_t bh1 = *(const uint32_t*)(rH + boff + 16);
            uint32_t bl0 = *(const uint32_t*)(rL + boff);
            uint32_t bl1 = *(const uint32_t*)(rL + boff + 16);
            if (kt < 4) {
                mma16816(d0h, a0h[kt], bh0, bh1);
                mma16816(d0l, a0h[kt], bl0, bl1);
            }
            if (t > 0) {
                mma16816(d1h, a1h[kt], bh0, bh1);
                mma16816(d1l, a1h[kt], bl0, bl1);
            }
        }

        // ---- complete gate preactivations, transpose to elem owners ----
        float V0[4], V1[4];
        V0[0] = d0h[0] + d0l[0] + xgAa + bias0A;
        V0[1] = d0h[1] + d0l[1] + xgBa + bias0A;
        V0[2] = d0h[2] + d0l[2] + xgAb + bias0B;
        V0[3] = d0h[3] + d0l[3] + xgBb + bias0B;
        transpose4(V0, gg);
        if (t > 0) {
            V1[0] = d1h[0] + d1l[0] + bias1A;
            V1[1] = d1h[1] + d1l[1] + bias1A;
            V1[2] = d1h[2] + d1l[2] + bias1B;
            V1[3] = d1h[3] + d1l[3] + bias1B;
            transpose4(V1, gg);
        }

        // ---- elem0(t): c0 update, h0(t) -> write buf atom0 ----
        {
            float iv = sigm_(V0[0]);
            float fv = sigm_(V0[1]);
            float gv = tanha(V0[2]);
            float ov = sigm_(V0[3]);
            c0 = fv * c0 + iv * gv;
            float hv = ov * tanha(c0);
            __nv_bfloat16 hi, lo; split_bf16(hv, hi, lo);
            *(__nv_bfloat16*)(wH + bT * B1S + hT * 2) = hi;
            *(__nv_bfloat16*)(wL + bT * B1S + hT * 2) = lo;
        }
        // ---- elem1(t-1): c1 update, h1(t-1) -> write buf atom1 ----
        if (t > 0) {
            float iv = sigm_(V1[0]);
            float fv = sigm_(V1[1]);
            float gv = tanha(V1[2]);
            float ov = sigm_(V1[3]);
            c1 = fv * c1 + iv * gv;
            float hv = ov * tanha(c1);
            __nv_bfloat16 hi, lo; split_bf16(hv, hi, lo);
            *(__nv_bfloat16*)(wH + bT * B1S + 128 + hT * 2) = hi;
            *(__nv_bfloat16*)(wL + bT * B1S + 128 + hT * 2) = lo;
        } else {
            // carry h1(-1) = 0 into the write buffer (already zeroed) - nothing to do
        }

        if (doPre) {
            int b = tid >> 1, qq = tid & 1;
            *(float4*)(xw + b * 8 + qq * 4) = xpre;
        }
        __syncthreads();
    }

    // ===== EPILOGUE: GEMM1(511) + elem1(511) + FC =====
    {
        const char* rH = smem + SM_B1H;        // phase 511 wrote buffer 0
        const char* rL = smem + SM_B1L;
        float d1h[4] = {0,0,0,0}, d1l[4] = {0,0,0,0};
        #pragma unroll
        for (int kt = 0; kt < 8; kt++) {
            uint32_t boff = bn * B1S + kt * 32 + bq * 4;
            uint32_t bh0 = *(const uint32_t*)(rH + boff);
            uint32_t bh1 = *(const uint32_t*)(rH + boff + 16);
            uint32_t bl0 = *(const uint32_t*)(rL + boff);
            uint32_t bl1 = *(const uint32_t*)(rL + boff + 16);
            mma16816(d1h, a1h[kt], bh0, bh1);
            mma16816(d1l, a1h[kt], bl0, bl1);
        }
        float V1[4];
        V1[0] = d1h[0] + d1l[0] + bias1A;
        V1[1] = d1h[1] + d1l[1] + bias1A;
        V1[2] = d1h[2] + d1l[2] + bias1B;
        V1[3] = d1h[3] + d1l[3] + bias1B;
        transpose4(V1, gg);
        float iv = sigm_(V1[0]);
        float fv = sigm_(V1[1]);
        float gv = tanha(V1[2]);
        float ov = sigm_(V1[3]);
        c1 = fv * c1 + iv * gv;
        h1f[bT * HID + hT] = ov * tanha(c1);
    }
    __syncthreads();

    if (tid < BT * ODIM) {
        int b = tid / ODIM, o = tid % ODIM;
        const float* hrow = h1f + b * HID;
        const float* wrow = w_fc + o * HID;
        float s = b_fc[o];
        #pragma unroll 16
        for (int k = 0; k < HID; k++) s = fmaf(hrow[k], wrow[k], s);
        out[(size_t)(b0 + b) * ODIM + o] = s;
    }
}

extern "C" void kernel_launch(void* const* d_in, const int* in_sizes, int n_in,
                              void* d_out, int out_size)
{
    (void)in_sizes; (void)n_in; (void)out_size;
    const float* x     = (const float*)d_in[0];
    const float* w_ih0 = (const float*)d_in[1];
    const float* w_hh0 = (const float*)d_in[2];
    const float* b_ih0 = (const float*)d_in[3];
    const float* b_hh0 = (const float*)d_in[4];
    const float* w_ih1 = (const float*)d_in[5];
    const float* w_hh1 = (const float*)d_in[6];
    const float* b_ih1 = (const float*)d_in[7];
    const float* b_hh1 = (const float*)d_in[8];
    const float* w_fc  = (const float*)d_in[9];
    const float* b_fc  = (const float*)d_in[10];

    cudaFuncSetAttribute(lstm_wmma_kernel,
                         cudaFuncAttributeMaxDynamicSharedMemorySize, SMEM_BYTES);
    lstm_wmma_kernel<<<NB, NTHREADS, SMEM_BYTES>>>(
        x, w_ih0, w_hh0, b_ih0, b_hh0, w_ih1, w_hh1, b_ih1, b_hh1, w_fc, b_fc,
        (float*)d_out);
}